// round 5
// baseline (speedup 1.0000x reference)
#include <cuda_runtime.h>
#include <cstdint>

#define Bb 2
#define Ss 2048
#define Dd 2048
#define Hh 16
#define HD 128
#define Mtot (Bb*Ss)

// Quad-tf32 global scratch. Within each 16-k block of a logical row, element k
// is stored at offset (k&3)*4 + ((k>>2)&3); blocks are contiguous. One LDS.128
// yields mma fragments for two k-steps.
// XP/AP: [Mtot][2048]            addr = m*2048 + (k>>4)*16 + (k&3)*4 + ((k>>2)&3)
// WP:    [K/16][N][16]           addr = (k>>4)*32768 + n*16 + (k&3)*4 + ((k>>2)&3)
// QP/KP: [bh][s][128 d-quads]    addr = (bh*2048+s)*128 + quad(d)
// VP:    [bh][d][2048 s-quads]   addr = (bh*128+d)*2048 + quad(s)
__device__ float g_XP[(size_t)Mtot * Dd];
__device__ float g_WPq[(size_t)Dd * Dd];
__device__ float g_WPk[(size_t)Dd * Dd];
__device__ float g_WPv[(size_t)Dd * Dd];
__device__ float g_WPd[(size_t)Dd * Dd];
__device__ float g_QP[(size_t)Mtot * Dd];
__device__ float g_KP[(size_t)Mtot * Dd];
__device__ float g_VP[(size_t)Mtot * Dd];
__device__ float g_AP[(size_t)Mtot * Dd];

__device__ __forceinline__ float to_tf32(float x) {
    float r;
    asm("cvt.rna.tf32.f32 %0, %1;" : "=f"(r) : "f"(x));
    return r;
}
__device__ __forceinline__ uint32_t u32(float x) { return __float_as_uint(x); }

__device__ __forceinline__ void mma8(float* c, const uint32_t* a, const uint32_t* b) {
    asm volatile(
        "mma.sync.aligned.m16n8k8.row.col.f32.tf32.tf32.f32 "
        "{%0,%1,%2,%3}, {%4,%5,%6,%7}, {%8,%9}, {%0,%1,%2,%3};"
        : "+f"(c[0]), "+f"(c[1]), "+f"(c[2]), "+f"(c[3])
        : "r"(a[0]), "r"(a[1]), "r"(a[2]), "r"(a[3]), "r"(b[0]), "r"(b[1]));
}
__device__ __forceinline__ void cpa16(void* dst, const void* src) {
    uint32_t d = (uint32_t)__cvta_generic_to_shared(dst);
    asm volatile("cp.async.cg.shared.global [%0], [%1], 16;" :: "r"(d), "l"(src));
}
#define CP_COMMIT asm volatile("cp.async.commit_group;")
#define CP_WAIT1  asm volatile("cp.async.wait_group 1;")
#define CP_WAIT0  asm volatile("cp.async.wait_group 0;")

__device__ __forceinline__ int quad16(int c) {
    return ((c >> 4) << 4) | ((c & 3) << 2) | ((c >> 2) & 3);
}

// ---------------------------------------------------------------------------
// Prep kernels: coalesced load -> smem permute -> coalesced float4 store.
// ---------------------------------------------------------------------------
__global__ void xprep(const float* __restrict__ X, float* __restrict__ XP) {
    __shared__ float s[2048];
    const int m = blockIdx.x;
    const int tid = threadIdx.x;
    const float* src = X + (size_t)m * 2048;
    float* dst = XP + (size_t)m * 2048;
#pragma unroll
    for (int i = 0; i < 2; i++) {
        int f = i * 256 + tid;
        *(float4*)(s + f * 4) = *(const float4*)(src + f * 4);
    }
    __syncthreads();
#pragma unroll
    for (int i = 0; i < 2; i++) {
        int f = i * 256 + tid;           // output float4 index
        int b = (f >> 2) * 16 + (f & 3); // k base = kb*16 + lc
        float4 v = make_float4(to_tf32(s[b]), to_tf32(s[b + 4]),
                               to_tf32(s[b + 8]), to_tf32(s[b + 12]));
        *(float4*)(dst + f * 4) = v;
    }
}

__global__ void wprep(const float* __restrict__ W, float* __restrict__ WP) {
    __shared__ float s[16 * 132];
    const int kb = blockIdx.y;          // 0..127
    const int n0 = blockIdx.x * 128;    // n chunk
    const int tid = threadIdx.x;
#pragma unroll
    for (int i = 0; i < 2; i++) {
        int f = i * 256 + tid;          // 512 float4 loads: 16 rows x 128 cols
        int r = f >> 5, c4 = (f & 31) * 4;
        float4 v = *(const float4*)(W + (size_t)(kb * 16 + r) * 2048 + n0 + c4);
        *(float4*)(s + r * 132 + c4) = v;
    }
    __syncthreads();
#pragma unroll
    for (int i = 0; i < 2; i++) {
        int f = i * 256 + tid;          // 512 output float4
        int n = f >> 2, lc = f & 3;
        float4 v = make_float4(to_tf32(s[lc * 132 + n]),
                               to_tf32(s[(lc + 4) * 132 + n]),
                               to_tf32(s[(lc + 8) * 132 + n]),
                               to_tf32(s[(lc + 12) * 132 + n]));
        *(float4*)(WP + (size_t)kb * 32768 + (size_t)n0 * 16 + f * 4) = v;
    }
}

// ---------------------------------------------------------------------------
// Pipelined tf32 GEMM on quad operands. BM=BN=128, BK=32, 8 warps (4m x 2n).
// As/Bs: [128][48] floats (32 used + 16 pad; stride%32==16 -> CF LDS.128).
// Per BK32 per warp: 24 LDS.128 + 64 HMMA.
// modes: 0=plain C fp32; 1=Q->QP (pre-scaled); 2=K->k_out+KP; 3=V->v_out+VP
// ---------------------------------------------------------------------------
#define GSTR 48
#define GBUF (128 * GSTR)

__global__ __launch_bounds__(256, 2)
void gemm_tc(const float* __restrict__ Ap, const float* __restrict__ WP,
             const float* __restrict__ bias, float* __restrict__ Craw,
             float* __restrict__ Cpair, int mode)
{
    extern __shared__ float smf[];

    const int tid  = threadIdx.x;
    const int lane = tid & 31;
    const int wid  = tid >> 5;
    const int mb   = (wid >> 1) * 32;
    const int nb   = (wid & 1) * 64;
    const int lr   = lane >> 2;
    const int lc   = lane & 3;
    const int bx   = blockIdx.x;
    const int by   = blockIdx.y;

    float acc[2][8][4];
#pragma unroll
    for (int f = 0; f < 2; f++)
#pragma unroll
        for (int g = 0; g < 8; g++)
#pragma unroll
            for (int t = 0; t < 4; t++) acc[f][g][t] = 0.f;

    auto issue = [&](int kt, int buf) {
        float* As = smf + buf * 2 * GBUF;
        float* Bs = As + GBUF;
#pragma unroll
        for (int j = 0; j < 4; j++) {
            int idx = j * 256 + tid;
            int m = idx >> 3, t8 = idx & 7;
            cpa16(As + m * GSTR + t8 * 4,
                  Ap + (size_t)(by * 128 + m) * 2048 + kt * 32 + t8 * 4);
        }
#pragma unroll
        for (int j = 0; j < 4; j++) {
            int idx = j * 256 + tid;
            int n = idx >> 3, t8 = idx & 7;
            cpa16(Bs + n * GSTR + t8 * 4,
                  WP + (size_t)(kt * 2 + (t8 >> 2)) * 32768 +
                       (size_t)(bx * 128 + n) * 16 + (t8 & 3) * 4);
        }
    };

    issue(0, 0);
    CP_COMMIT;

    for (int kt = 0; kt < 64; kt++) {
        CP_WAIT0;
        __syncthreads();
        if (kt < 63) { issue(kt + 1, (kt + 1) & 1); CP_COMMIT; }

        const float* As = smf + (kt & 1) * 2 * GBUF;
        const float* Bs = As + GBUF;

#pragma unroll
        for (int kbq = 0; kbq < 2; kbq++) {
            const int base = kbq * 16 + lc * 4;
            float4 q0 = *(const float4*)(As + (mb + lr) * GSTR + base);
            float4 q1 = *(const float4*)(As + (mb + lr + 8) * GSTR + base);
            float4 q2 = *(const float4*)(As + (mb + 16 + lr) * GSTR + base);
            float4 q3 = *(const float4*)(As + (mb + 24 + lr) * GSTR + base);
            uint32_t ae0[4] = {u32(q0.x), u32(q1.x), u32(q0.y), u32(q1.y)};
            uint32_t ao0[4] = {u32(q0.z), u32(q1.z), u32(q0.w), u32(q1.w)};
            uint32_t ae1[4] = {u32(q2.x), u32(q3.x), u32(q2.y), u32(q3.y)};
            uint32_t ao1[4] = {u32(q2.z), u32(q3.z), u32(q2.w), u32(q3.w)};
#pragma unroll
            for (int g = 0; g < 8; g++) {
                float4 bv = *(const float4*)(Bs + (nb + g * 8 + lr) * GSTR + base);
                uint32_t be[2] = {u32(bv.x), u32(bv.y)};
                uint32_t bo[2] = {u32(bv.z), u32(bv.w)};
                mma8(acc[0][g], ae0, be);
                mma8(acc[1][g], ae1, be);
                mma8(acc[0][g], ao0, bo);
                mma8(acc[1][g], ao1, bo);
            }
        }
        __syncthreads();
    }

    const float qscale = 0.08838834764831845f;  // folded into Q when mode==1
#pragma unroll
    for (int f = 0; f < 2; f++) {
#pragma unroll
        for (int g = 0; g < 8; g++) {
#pragma unroll
            for (int ii = 0; ii < 2; ii++) {
                int row = by * 128 + mb + f * 16 + lr + 8 * ii;
#pragma unroll
                for (int jj = 0; jj < 2; jj++) {
                    int col = bx * 128 + nb + g * 8 + lc * 2 + jj;
                    float v = acc[f][g][ii * 2 + jj] + bias[col];
                    if (mode == 0) {
                        Craw[(size_t)row * Dd + col] = v;
                    } else {
                        int b_ = row >> 11, s_ = row & 2047;
                        int h_ = col >> 7,  d_ = col & 127;
                        size_t bh = (size_t)(b_ * Hh + h_);
                        if (mode >= 2) Craw[(bh * Ss + s_) * HD + d_] = v;
                        if (mode == 3) {
                            Cpair[(bh * 128 + d_) * 2048 + quad16(s_)] = to_tf32(v);
                        } else {
                            float tv = (mode == 1) ? to_tf32(v * qscale) : to_tf32(v);
                            Cpair[(bh * Ss + s_) * 128 + quad16(d_)] = tv;
                        }
                    }
                }
            }
        }
    }
}

// ---------------------------------------------------------------------------
// Single-pass tf32 flash attention on quad operands.
// Grid (S/128, B*H), 8 warps x 16 q-rows, KV tiles 64, double-buffered.
// sQ [128][144], sK 2x[64][144], sV 2x[128][80]  => 224 KB smem.
// Per warp per tile: 144 LDS.128 + 256 HMMA.
// ---------------------------------------------------------------------------
#define AQSTR 144
#define AKSTR 144
#define AVSTR 80
#define AQ_ (128 * AQSTR)
#define AK_ (64 * AKSTR)
#define AV_ (128 * AVSTR)

__global__ __launch_bounds__(256)
void attn_tc(const float* __restrict__ QP, const float* __restrict__ KP,
             const float* __restrict__ VP, float* __restrict__ AP)
{
    extern __shared__ float smf[];
    float* sQ = smf;
    float* sK = sQ + AQ_;
    float* sV = sK + 2 * AK_;

    const int qt  = (gridDim.x - 1) - blockIdx.x;
    const int bh  = blockIdx.y;
    const int tid = threadIdx.x;
    const int lane = tid & 31;
    const int wid  = tid >> 5;
    const int lr   = lane >> 2;
    const int lc   = lane & 3;
    const int m_off = wid * 16;

    const float* Qg = QP + ((size_t)bh * Ss + (size_t)qt * 128) * 128;
    const float* Kg = KP + (size_t)bh * Ss * 128;
    const float* Vg = VP + (size_t)bh * 128 * 2048;

#pragma unroll
    for (int i = 0; i < 16; i++) {
        int idx = i * 256 + tid;
        int row = idx >> 5, c = idx & 31;
        cpa16(sQ + row * AQSTR + c * 4, Qg + (size_t)row * 128 + c * 4);
    }
#pragma unroll
    for (int i = 0; i < 8; i++) {
        int idx = i * 256 + tid;
        int row = idx >> 5, c = idx & 31;
        cpa16(sK + row * AKSTR + c * 4, Kg + (size_t)row * 128 + c * 4);
    }
#pragma unroll
    for (int i = 0; i < 8; i++) {
        int idx = i * 256 + tid;
        int d = idx >> 4, c = idx & 15;
        cpa16(sV + d * AVSTR + c * 4, Vg + (size_t)d * 2048 + c * 4);
    }
    CP_COMMIT;

    float o[16][4];
#pragma unroll
    for (int n = 0; n < 16; n++)
#pragma unroll
        for (int j = 0; j < 4; j++) o[n][j] = 0.f;
    float m0 = -1e30f, m1 = -1e30f, l0 = 0.f, l1 = 0.f;

    const int tmax = 2 * qt + 1;
    const int warp_max_row = qt * 128 + m_off + 15;

    for (int t = 0; t <= tmax; t++) {
        const int buf = t & 1;
        if (t < tmax) {
            const int nb2 = (t + 1) & 1;
            float* dK = sK + nb2 * AK_;
            float* dV = sV + nb2 * AV_;
            const float* gK = Kg + (size_t)(t + 1) * 64 * 128;
            const float* gV = Vg + (size_t)(t + 1) * 64;
#pragma unroll
            for (int i = 0; i < 8; i++) {
                int idx = i * 256 + tid;
                int row = idx >> 5, c = idx & 31;
                cpa16(dK + row * AKSTR + c * 4, gK + (size_t)row * 128 + c * 4);
            }
#pragma unroll
            for (int i = 0; i < 8; i++) {
                int idx = i * 256 + tid;
                int d = idx >> 4, c = idx & 15;
                cpa16(dV + d * AVSTR + c * 4, gV + (size_t)d * 2048 + c * 4);
            }
            CP_COMMIT;
            CP_WAIT1;
        } else {
            CP_WAIT0;
        }
        __syncthreads();

        if (t * 64 <= warp_max_row) {   // skip fully-masked warp tiles
            const float* sKb = sK + buf * AK_;
            const float* sVb = sV + buf * AV_;

            // ---- S = Q @ K^T (Q pre-scaled), warp tile 16x64 ----
            float c[8][4];
#pragma unroll
            for (int n = 0; n < 8; n++)
#pragma unroll
                for (int j = 0; j < 4; j++) c[n][j] = 0.f;

#pragma unroll
            for (int kp = 0; kp < 8; kp++) {
                const int base = kp * 16 + lc * 4;
                float4 qa = *(const float4*)(sQ + (m_off + lr) * AQSTR + base);
                float4 qb = *(const float4*)(sQ + (m_off + lr + 8) * AQSTR + base);
                uint32_t ae[4] = {u32(qa.x), u32(qb.x), u32(qa.y), u32(qb.y)};
                uint32_t ao[4] = {u32(qa.z), u32(qb.z), u32(qa.w), u32(qb.w)};
#pragma unroll
                for (int nf = 0; nf < 8; nf++) {
                    float4 kv = *(const float4*)(sKb + (nf * 8 + lr) * AKSTR + base);
                    uint32_t be[2] = {u32(kv.x), u32(kv.y)};
                    uint32_t bo[2] = {u32(kv.z), u32(kv.w)};
                    mma8(c[nf], ae, be);
                    mma8(c[nf], ao, bo);
                }
            }

            // ---- causal mask (only near diagonal) ----
            if (t * 64 + 63 > qt * 128 + m_off) {
#pragma unroll
                for (int nf = 0; nf < 8; nf++) {
#pragma unroll
                    for (int j = 0; j < 4; j++) {
                        int col = t * 64 + nf * 8 + 2 * lc + (j & 1);
                        int row = qt * 128 + m_off + lr + 8 * (j >> 1);
                        if (col > row) c[nf][j] = -1e30f;
                    }
                }
            }

            // ---- online softmax (rows lr, lr+8) ----
            float mt0 = -1e30f, mt1 = -1e30f;
#pragma unroll
            for (int nf = 0; nf < 8; nf++) {
                mt0 = fmaxf(mt0, fmaxf(c[nf][0], c[nf][1]));
                mt1 = fmaxf(mt1, fmaxf(c[nf][2], c[nf][3]));
            }
#pragma unroll
            for (int d = 1; d <= 2; d <<= 1) {
                mt0 = fmaxf(mt0, __shfl_xor_sync(0xffffffffu, mt0, d));
                mt1 = fmaxf(mt1, __shfl_xor_sync(0xffffffffu, mt1, d));
            }
            float nm0 = fmaxf(m0, mt0), nm1 = fmaxf(m1, mt1);
            float corr0 = __expf(m0 - nm0), corr1 = __expf(m1 - nm1);
            m0 = nm0; m1 = nm1;

            float s0 = 0.f, s1 = 0.f;
#pragma unroll
            for (int nf = 0; nf < 8; nf++) {
                c[nf][0] = __expf(c[nf][0] - nm0); s0 += c[nf][0];
                c[nf][1] = __expf(c[nf][1] - nm0); s0 += c[nf][1];
                c[nf][2] = __expf(c[nf][2] - nm1); s1 += c[nf][2];
                c[nf][3] = __expf(c[nf][3] - nm1); s1 += c[nf][3];
            }
#pragma unroll
            for (int d = 1; d <= 2; d <<= 1) {
                s0 += __shfl_xor_sync(0xffffffffu, s0, d);
                s1 += __shfl_xor_sync(0xffffffffu, s1, d);
            }
            l0 = l0 * corr0 + s0;
            l1 = l1 * corr1 + s1;

            if (__any_sync(0xffffffffu, (corr0 != 1.f) || (corr1 != 1.f))) {
#pragma unroll
                for (int n = 0; n < 16; n++) {
                    o[n][0] *= corr0; o[n][1] *= corr0;
                    o[n][2] *= corr1; o[n][3] *= corr1;
                }
            }

            // ---- O += P @ V, warp tile 16x128 ----
#pragma unroll
            for (int kp = 0; kp < 4; kp++) {
                const int src0 = 4 * lr + (lc >> 1);
                const int src1 = src0 + 2;
                uint32_t a0[4], a1[4];
#pragma unroll
                for (int h = 0; h < 2; h++) {        // h=0 -> ks=2kp, h=1 -> ks=2kp+1
                    float* cc = c[2 * kp + h];
                    float v00 = __shfl_sync(0xffffffffu, cc[0], src0);
                    float v01 = __shfl_sync(0xffffffffu, cc[1], src0);
                    float v20 = __shfl_sync(0xffffffffu, cc[2], src0);
                    float v21 = __shfl_sync(0xffffffffu, cc[3], src0);
                    float w00 = __shfl_sync(0xffffffffu, cc[0], src1);
                    float w01 = __shfl_sync(0xffffffffu, cc[1], src1);
                    float w20 = __shfl_sync(0xffffffffu, cc[2], src1);
                    float w21 = __shfl_sync(0xffffffffu, cc[3], src1);
                    uint32_t* a = h ? a1 : a0;
                    a[0] = u32(to_tf32((lc & 1) ? v01 : v00));
                    a[1] = u32(to_tf32((lc & 1) ? v21 : v20));
                    a[2] = u32(to_tf32((lc & 1) ? w01 : w00));
                    a[3] = u32(to_tf32((lc & 1) ? w21 : w20));
                }
                const int base = kp * 16 + lc * 4;
#pragma unroll
                for (int nf = 0; nf < 16; nf++) {
                    float4 vv = *(const float4*)(sVb + (nf * 8 + lr) * AVSTR + base);
                    uint32_t be[2] = {u32(vv.x), u32(vv.y)};
                    uint32_t bo[2] = {u32(vv.z), u32(vv.w)};
                    mma8(o[nf], a0, be);
                    mma8(o[nf], a1, bo);
                }
            }
        }
        __syncthreads();
    }

    // ---- epilogue: normalize, write quad-layout AP ----
    const float inv0 = 1.0f / l0;
    const float inv1 = 1.0f / l1;
    const int b = bh / Hh;
    const int h = bh % Hh;
    const size_t mrow0 = (size_t)b * 2048 + qt * 128 + m_off + lr;
    const size_t mrow1 = mrow0 + 8;
#pragma unroll
    for (int nf = 0; nf < 16; nf++) {
#pragma unroll
        for (int jj = 0; jj < 2; jj++) {
            int col = h * 128 + nf * 8 + 2 * lc + jj;
            int cq = quad16(col);
            AP[mrow0 * 2048 + cq] = to_tf32(o[nf][jj] * inv0);
            AP[mrow1 * 2048 + cq] = to_tf32(o[nf][2 + jj] * inv1);
        }
    }
}

// ---------------------------------------------------------------------------

extern "C" void kernel_launch(void* const* d_in, const int* in_sizes, int n_in,
                              void* d_out, int out_size)
{
    const float* x  = (const float*)d_in[0];
    const float* Wq = (const float*)d_in[1];
    const float* bq = (const float*)d_in[2];
    const float* Wk = (const float*)d_in[3];
    const float* bk = (const float*)d_in[4];
    const float* Wv = (const float*)d_in[5];
    const float* bv = (const float*)d_in[6];
    const float* Wd = (const float*)d_in[7];
    const float* bd = (const float*)d_in[8];

    float* out = (float*)d_out;
    float* a_out = out;
    float* k_out = out + (size_t)Bb * Ss * Dd;
    float* v_out = k_out + (size_t)Bb * Ss * Dd;

    float *xp, *wpq, *wpk, *wpv, *wpd, *qp, *kp, *vp, *ap;
    cudaGetSymbolAddress((void**)&xp,  g_XP);
    cudaGetSymbolAddress((void**)&wpq, g_WPq);
    cudaGetSymbolAddress((void**)&wpk, g_WPk);
    cudaGetSymbolAddress((void**)&wpv, g_WPv);
    cudaGetSymbolAddress((void**)&wpd, g_WPd);
    cudaGetSymbolAddress((void**)&qp,  g_QP);
    cudaGetSymbolAddress((void**)&kp,  g_KP);
    cudaGetSymbolAddress((void**)&vp,  g_VP);
    cudaGetSymbolAddress((void**)&ap,  g_AP);

    xprep<<<Mtot, 256>>>(x, xp);
    wprep<<<dim3(16, 128), 256>>>(Wq, wpq);
    wprep<<<dim3(16, 128), 256>>>(Wk, wpk);
    wprep<<<dim3(16, 128), 256>>>(Wv, wpv);
    wprep<<<dim3(16, 128), 256>>>(Wd, wpd);

    dim3 gg(Dd / 128, Mtot / 128);
    size_t gsm = 4 * (size_t)GBUF * sizeof(float);
    cudaFuncSetAttribute(gemm_tc, cudaFuncAttributeMaxDynamicSharedMemorySize, (int)gsm);

    gemm_tc<<<gg, 256, gsm>>>(xp, wpq, bq, nullptr, qp, 1);
    gemm_tc<<<gg, 256, gsm>>>(xp, wpk, bk, k_out, kp, 2);
    gemm_tc<<<gg, 256, gsm>>>(xp, wpv, bv, v_out, vp, 3);

    size_t asmem = (size_t)(AQ_ + 2 * AK_ + 2 * AV_) * sizeof(float);
    cudaFuncSetAttribute(attn_tc, cudaFuncAttributeMaxDynamicSharedMemorySize, (int)asmem);
    attn_tc<<<dim3(Ss / 128, Bb * Hh), 256, asmem>>>(qp, kp, vp, ap);

    gemm_tc<<<gg, 256, gsm>>>(ap, wpd, bd, a_out, nullptr, 0);
}

// round 7
// speedup vs baseline: 1.1346x; 1.1346x over previous
#include <cuda_runtime.h>
#include <cstdint>

#define Bb 2
#define Ss 2048
#define Dd 2048
#define Hh 16
#define HD 128
#define Mtot (Bb*Ss)

// Paired-tf32 global scratch (R3 layout).
// XP/AP: [Mtot][2048] floats:   addr = m*2048 + (k>>3)*8 + (k&3)*2 + ((k>>2)&1)
// WP:    [K/8][N][8 floats]:    addr = (k>>3)*16384 + n*8 + (k&3)*2 + ((k>>2)&1)
// QP/KP: per bh [Ss][128]:      addr = (bh*Ss+s)*128 + (d>>3)*8 + (d&3)*2 + ((d>>2)&1)
// VP:    per bh [128 d][2048]:  addr = (bh*128+d)*2048 + (s>>3)*8 + (s&3)*2 + ((s>>2)&1)
__device__ float g_XP[(size_t)Mtot * Dd];
__device__ float g_WPq[(size_t)Dd * Dd];
__device__ float g_WPk[(size_t)Dd * Dd];
__device__ float g_WPv[(size_t)Dd * Dd];
__device__ float g_WPd[(size_t)Dd * Dd];
__device__ float g_QP[(size_t)Mtot * Dd];
__device__ float g_KP[(size_t)Mtot * Dd];
__device__ float g_VP[(size_t)Mtot * Dd];
__device__ float g_AP[(size_t)Mtot * Dd];

__device__ __forceinline__ float to_tf32(float x) {
    float r;
    asm("cvt.rna.tf32.f32 %0, %1;" : "=f"(r) : "f"(x));
    return r;
}
__device__ __forceinline__ uint32_t u32(float x) { return __float_as_uint(x); }

__device__ __forceinline__ void mma8(float* c, const uint32_t* a, const uint32_t* b) {
    asm volatile(
        "mma.sync.aligned.m16n8k8.row.col.f32.tf32.tf32.f32 "
        "{%0,%1,%2,%3}, {%4,%5,%6,%7}, {%8,%9}, {%0,%1,%2,%3};"
        : "+f"(c[0]), "+f"(c[1]), "+f"(c[2]), "+f"(c[3])
        : "r"(a[0]), "r"(a[1]), "r"(a[2]), "r"(a[3]), "r"(b[0]), "r"(b[1]));
}
__device__ __forceinline__ void cpa16(void* dst, const void* src) {
    uint32_t d = (uint32_t)__cvta_generic_to_shared(dst);
    asm volatile("cp.async.cg.shared.global [%0], [%1], 16;" :: "r"(d), "l"(src));
}
#define CP_COMMIT asm volatile("cp.async.commit_group;")
#define CP_WAIT1  asm volatile("cp.async.wait_group 1;")
#define CP_WAIT0  asm volatile("cp.async.wait_group 0;")

// ---------------------------------------------------------------------------
// Fast prep kernels: coalesced load -> padded smem -> contiguous 32B/thread
// stores in pair layout. (Scalar STS into padded smem: 16B-alignment of the
// padded addresses is NOT guaranteed, so no vector STS there.)
// ---------------------------------------------------------------------------
__global__ void xprep(const float* __restrict__ X, float* __restrict__ XP) {
    __shared__ float s[2048 + 256];            // addr(g) = g + (g>>3)
    const int m = blockIdx.x;
    const int tid = threadIdx.x;
    const float* src = X + (size_t)m * 2048;
#pragma unroll
    for (int i = 0; i < 2; i++) {
        int f = i * 256 + tid;                 // float4 index
        float4 v = *(const float4*)(src + f * 4);
        // the 4 padded slots are contiguous within an 8-block (g%8 in {0,4})
        float* d = s + f * 4 + (f >> 1);
        d[0] = v.x; d[1] = v.y; d[2] = v.z; d[3] = v.w;
    }
    __syncthreads();
    const float* b = s + tid * 9;              // 8 floats + 1 pad, CF reads
    float4 o0 = make_float4(to_tf32(b[0]), to_tf32(b[4]), to_tf32(b[1]), to_tf32(b[5]));
    float4 o1 = make_float4(to_tf32(b[2]), to_tf32(b[6]), to_tf32(b[3]), to_tf32(b[7]));
    float* dst = XP + (size_t)m * 2048 + tid * 8;
    *(float4*)(dst) = o0;
    *(float4*)(dst + 4) = o1;
}

__global__ void wprep(const float* __restrict__ W, float* __restrict__ WP) {
    __shared__ float s[8 * 260];
    const int n0 = blockIdx.x * 256;
    const int kb = blockIdx.y;                 // 0..255
    const int tid = threadIdx.x;
#pragma unroll
    for (int i = 0; i < 2; i++) {
        int f = i * 256 + tid;                 // 512 float4: 8 rows x 256 cols
        int r = f >> 6, c4 = (f & 63) * 4;
        float4 v = *(const float4*)(W + (size_t)(kb * 8 + r) * 2048 + n0 + c4);
        *(float4*)(s + r * 260 + c4) = v;      // 260 % 4 == 0 -> aligned
    }
    __syncthreads();
    const int n = tid;
    float4 o0 = make_float4(to_tf32(s[0 * 260 + n]), to_tf32(s[4 * 260 + n]),
                            to_tf32(s[1 * 260 + n]), to_tf32(s[5 * 260 + n]));
    float4 o1 = make_float4(to_tf32(s[2 * 260 + n]), to_tf32(s[6 * 260 + n]),
                            to_tf32(s[3 * 260 + n]), to_tf32(s[7 * 260 + n]));
    float* dst = WP + (size_t)kb * 16384 + (size_t)(n0 + n) * 8;
    *(float4*)(dst) = o0;
    *(float4*)(dst + 4) = o1;
}

// ---------------------------------------------------------------------------
// Pipelined tf32 GEMM on pre-paired operands (R3 schedule).
// BM=BN=128, BK=32, 256 thr = 8 warps (4m x 2n), warp 32x64.
// As: [128 m][20 float2], Bs: [4 kb][128 n][4 float2]
// modes: 0=plain C fp32; 1=Q->QP (qscale folded); 2=K->k_out+KP; 3=V->v_out+VP
// ---------------------------------------------------------------------------
#define ABUF2 (128*20)
#define BBUF2 (4*128*4)
#define GBUF2 (ABUF2 + BBUF2)

__global__ __launch_bounds__(256, 2)
void gemm_tc(const float* __restrict__ Ap, const float* __restrict__ WP,
             const float* __restrict__ bias, float* __restrict__ Craw,
             float* __restrict__ Cpair, int mode)
{
    extern __shared__ float2 sm2[];

    const int tid  = threadIdx.x;
    const int lane = tid & 31;
    const int wid  = tid >> 5;
    const int mb   = (wid >> 1) * 32;
    const int nb   = (wid & 1) * 64;
    const int lr   = lane >> 2;
    const int lc   = lane & 3;
    const int bx   = blockIdx.x;
    const int by   = blockIdx.y;

    float acc[2][8][4];
#pragma unroll
    for (int f = 0; f < 2; f++)
#pragma unroll
        for (int g = 0; g < 8; g++)
#pragma unroll
            for (int t = 0; t < 4; t++) acc[f][g][t] = 0.f;

    auto issue = [&](int kt, int buf) {
        float2* As = sm2 + buf * GBUF2;
        float2* Bs = As + ABUF2;
#pragma unroll
        for (int j = 0; j < 4; j++) {
            int idx = j * 256 + tid;
            int m   = idx >> 3;
            int ch  = idx & 7;
            cpa16(As + m * 20 + ch * 2,
                  Ap + (size_t)(by * 128 + m) * 2048 + kt * 32 + ch * 4);
        }
#pragma unroll
        for (int j = 0; j < 4; j++) {
            int idx = j * 256 + tid;
            int kb  = idx >> 8;
            int r   = idx & 255;
            int n   = r >> 1;
            int ch  = r & 1;
            cpa16(Bs + kb * 512 + n * 4 + ch * 2,
                  WP + (size_t)(kt * 4 + kb) * 16384 + (size_t)(bx * 128 + n) * 8 + ch * 4);
        }
    };

    issue(0, 0);
    CP_COMMIT;

    for (int kt = 0; kt < 64; kt++) {
        CP_WAIT0;
        __syncthreads();
        if (kt < 63) { issue(kt + 1, (kt + 1) & 1); CP_COMMIT; }

        const float2* As = sm2 + (kt & 1) * GBUF2;
        const float2* Bs = As + ABUF2;

#pragma unroll
        for (int ks = 0; ks < 4; ks++) {
            const float2* ap = As + (mb + lr) * 20 + ks * 4 + lc;
            float2 x00 = ap[0], x01 = ap[160], x10 = ap[320], x11 = ap[480];
            uint32_t a0[4] = {u32(x00.x), u32(x01.x), u32(x00.y), u32(x01.y)};
            uint32_t a1[4] = {u32(x10.x), u32(x11.x), u32(x10.y), u32(x11.y)};
            const float2* bp = Bs + ks * 512 + (nb + lr) * 4 + lc;
#pragma unroll
            for (int g = 0; g < 8; g++) {
                float2 bv = bp[g * 32];
                uint32_t b[2] = {u32(bv.x), u32(bv.y)};
                mma8(acc[0][g], a0, b);
                mma8(acc[1][g], a1, b);
            }
        }
        __syncthreads();
    }

    const float qscale = 0.08838834764831845f;   // folded into Q when mode==1
#pragma unroll
    for (int f = 0; f < 2; f++) {
#pragma unroll
        for (int g = 0; g < 8; g++) {
#pragma unroll
            for (int ii = 0; ii < 2; ii++) {
                int row = by * 128 + mb + f * 16 + lr + 8 * ii;
#pragma unroll
                for (int jj = 0; jj < 2; jj++) {
                    int col = bx * 128 + nb + g * 8 + lc * 2 + jj;
                    float v = acc[f][g][ii * 2 + jj] + bias[col];
                    if (mode == 0) {
                        Craw[(size_t)row * Dd + col] = v;
                    } else {
                        int b_ = row >> 11, s_ = row & 2047;
                        int h_ = col >> 7,  d_ = col & 127;
                        size_t bh = (size_t)(b_ * Hh + h_);
                        if (mode >= 2) Craw[(bh * Ss + s_) * HD + d_] = v;
                        if (mode == 3) {
                            Cpair[(bh * 128 + d_) * 2048 +
                                  (s_ >> 3) * 8 + (s_ & 3) * 2 + ((s_ >> 2) & 1)] = to_tf32(v);
                        } else {
                            float tv = (mode == 1) ? to_tf32(v * qscale) : to_tf32(v);
                            Cpair[(bh * Ss + s_) * 128 +
                                  (d_ >> 3) * 8 + (d_ & 3) * 2 + ((d_ >> 2) & 1)] = tv;
                        }
                    }
                }
            }
        }
    }
}

// ---------------------------------------------------------------------------
// Single-pass tf32 flash attention on pre-paired operands (R3 schedule).
// Grid (S/128, B*H), 256 thr = 8 warps x 16 q-rows. KV tiles 64, double-buffered.
// Q pre-scaled by 1/sqrt(hd) in the Q GEMM. Masked warp-tiles skipped.
// ---------------------------------------------------------------------------
#define QS2 68
#define KS2 68
#define VS2 36
#define SQ2 (128*QS2)
#define SK2 (64*KS2)
#define SV2 (128*VS2)

__global__ __launch_bounds__(256)
void attn_tc(const float* __restrict__ QP, const float* __restrict__ KP,
             const float* __restrict__ VP, float* __restrict__ AP)
{
    extern __shared__ float2 sm2[];
    float2* sQ = sm2;                  // SQ2
    float2* sK = sQ + SQ2;             // 2*SK2
    float2* sV = sK + 2 * SK2;         // 2*SV2

    const int qt  = (gridDim.x - 1) - blockIdx.x;
    const int bh  = blockIdx.y;
    const int tid = threadIdx.x;
    const int lane = tid & 31;
    const int wid  = tid >> 5;
    const int lr   = lane >> 2;
    const int lc   = lane & 3;
    const int m_off = wid * 16;

    const float* Qg = QP + ((size_t)bh * Ss + (size_t)qt * 128) * 128;
    const float* Kg = KP + (size_t)bh * Ss * 128;
    const float* Vg = VP + (size_t)bh * 128 * 2048;

#pragma unroll
    for (int i = 0; i < 16; i++) {
        int idx = i * 256 + tid;
        int row = idx >> 5;
        int ch  = idx & 31;
        cpa16(sQ + row * QS2 + ch * 2, Qg + (size_t)row * 128 + ch * 4);
    }
#pragma unroll
    for (int i = 0; i < 8; i++) {
        int idx = i * 256 + tid;
        int row = idx >> 5;
        int ch  = idx & 31;
        cpa16(sK + row * KS2 + ch * 2, Kg + (size_t)row * 128 + ch * 4);
    }
#pragma unroll
    for (int i = 0; i < 8; i++) {
        int idx = i * 256 + tid;
        int d   = idx >> 4;
        int ch  = idx & 15;
        cpa16(sV + d * VS2 + ch * 2, Vg + (size_t)d * 2048 + ch * 4);
    }
    CP_COMMIT;

    float o[16][4];
#pragma unroll
    for (int n = 0; n < 16; n++)
#pragma unroll
        for (int j = 0; j < 4; j++) o[n][j] = 0.f;
    float m0 = -1e30f, m1 = -1e30f, l0 = 0.f, l1 = 0.f;

    const int tmax = 2 * qt + 1;
    const int warp_max_row = qt * 128 + m_off + 15;

    for (int t = 0; t <= tmax; t++) {
        const int buf = t & 1;
        if (t < tmax) {
            const int nb2 = (t + 1) & 1;
            float2* dK = sK + nb2 * SK2;
            float2* dV = sV + nb2 * SV2;
            const float* gK = Kg + (size_t)(t + 1) * 64 * 128;
            const float* gV = Vg + (size_t)(t + 1) * 64;
#pragma unroll
            for (int i = 0; i < 8; i++) {
                int idx = i * 256 + tid;
                int row = idx >> 5;
                int ch  = idx & 31;
                cpa16(dK + row * KS2 + ch * 2, gK + (size_t)row * 128 + ch * 4);
            }
#pragma unroll
            for (int i = 0; i < 8; i++) {
                int idx = i * 256 + tid;
                int d   = idx >> 4;
                int ch  = idx & 15;
                cpa16(dV + d * VS2 + ch * 2, gV + (size_t)d * 2048 + ch * 4);
            }
            CP_COMMIT;
            CP_WAIT1;
        } else {
            CP_WAIT0;
        }
        __syncthreads();

        if (t * 64 <= warp_max_row) {    // skip fully-masked warp tiles
            const float2* sKb = sK + buf * SK2;
            const float2* sVb = sV + buf * SV2;

            // ---- S = Q @ K^T (Q pre-scaled), warp tile 16x64 ----
            float c[8][4];
#pragma unroll
            for (int n = 0; n < 8; n++)
#pragma unroll
                for (int j = 0; j < 4; j++) c[n][j] = 0.f;

#pragma unroll
            for (int ks = 0; ks < 16; ks++) {
                const float2* qp = sQ + (m_off + lr) * QS2 + ks * 4 + lc;
                float2 q0 = qp[0], q1 = qp[8 * QS2];
                uint32_t a[4] = {u32(q0.x), u32(q1.x), u32(q0.y), u32(q1.y)};
                const float2* kp = sKb + lr * KS2 + ks * 4 + lc;
#pragma unroll
                for (int nf = 0; nf < 8; nf++) {
                    float2 bv = kp[nf * 8 * KS2];
                    uint32_t b[2] = {u32(bv.x), u32(bv.y)};
                    mma8(c[nf], a, b);
                }
            }

            // ---- causal mask ----
            if (t * 64 + 63 > qt * 128 + m_off) {
#pragma unroll
                for (int nf = 0; nf < 8; nf++) {
#pragma unroll
                    for (int j = 0; j < 4; j++) {
                        int col = t * 64 + nf * 8 + 2 * lc + (j & 1);
                        int row = qt * 128 + m_off + lr + 8 * (j >> 1);
                        if (col > row) c[nf][j] = -1e30f;
                    }
                }
            }

            // ---- online softmax (rows lr, lr+8) ----
            float mt0 = -1e30f, mt1 = -1e30f;
#pragma unroll
            for (int nf = 0; nf < 8; nf++) {
                mt0 = fmaxf(mt0, fmaxf(c[nf][0], c[nf][1]));
                mt1 = fmaxf(mt1, fmaxf(c[nf][2], c[nf][3]));
            }
#pragma unroll
            for (int d = 1; d <= 2; d <<= 1) {
                mt0 = fmaxf(mt0, __shfl_xor_sync(0xffffffffu, mt0, d));
                mt1 = fmaxf(mt1, __shfl_xor_sync(0xffffffffu, mt1, d));
            }
            float nm0 = fmaxf(m0, mt0), nm1 = fmaxf(m1, mt1);
            float corr0 = __expf(m0 - nm0), corr1 = __expf(m1 - nm1);
            m0 = nm0; m1 = nm1;

            float s0 = 0.f, s1 = 0.f;
#pragma unroll
            for (int nf = 0; nf < 8; nf++) {
                c[nf][0] = __expf(c[nf][0] - nm0); s0 += c[nf][0];
                c[nf][1] = __expf(c[nf][1] - nm0); s0 += c[nf][1];
                c[nf][2] = __expf(c[nf][2] - nm1); s1 += c[nf][2];
                c[nf][3] = __expf(c[nf][3] - nm1); s1 += c[nf][3];
            }
#pragma unroll
            for (int d = 1; d <= 2; d <<= 1) {
                s0 += __shfl_xor_sync(0xffffffffu, s0, d);
                s1 += __shfl_xor_sync(0xffffffffu, s1, d);
            }
            l0 = l0 * corr0 + s0;
            l1 = l1 * corr1 + s1;

#pragma unroll
            for (int n = 0; n < 16; n++) {
                o[n][0] *= corr0; o[n][1] *= corr0;
                o[n][2] *= corr1; o[n][3] *= corr1;
            }

            // ---- O += P @ V, warp tile 16x128 ----
#pragma unroll
            for (int ks = 0; ks < 8; ks++) {
                const int src0 = 4 * lr + (lc >> 1);
                const int src1 = src0 + 2;
                float v00 = __shfl_sync(0xffffffffu, c[ks][0], src0);
                float v01 = __shfl_sync(0xffffffffu, c[ks][1], src0);
                float v20 = __shfl_sync(0xffffffffu, c[ks][2], src0);
                float v21 = __shfl_sync(0xffffffffu, c[ks][3], src0);
                float w00 = __shfl_sync(0xffffffffu, c[ks][0], src1);
                float w01 = __shfl_sync(0xffffffffu, c[ks][1], src1);
                float w20 = __shfl_sync(0xffffffffu, c[ks][2], src1);
                float w21 = __shfl_sync(0xffffffffu, c[ks][3], src1);
                float a0f = (lc & 1) ? v01 : v00;
                float a1f = (lc & 1) ? v21 : v20;
                float a2f = (lc & 1) ? w01 : w00;
                float a3f = (lc & 1) ? w21 : w20;
                uint32_t a[4] = {u32(to_tf32(a0f)), u32(to_tf32(a1f)),
                                 u32(to_tf32(a2f)), u32(to_tf32(a3f))};
                const float2* vp = sVb + lr * VS2 + ks * 4 + lc;
#pragma unroll
                for (int nf = 0; nf < 16; nf++) {
                    float2 bv = vp[nf * 8 * VS2];
                    uint32_t b[2] = {u32(bv.x), u32(bv.y)};
                    mma8(o[nf], a, b);
                }
            }
        }
        __syncthreads();
    }

    // ---- epilogue: normalize, convert, write pre-paired AP ----
    const float inv0 = 1.0f / l0;
    const float inv1 = 1.0f / l1;
    const int b = bh / Hh;
    const int h = bh % Hh;
    const size_t mrow0 = (size_t)b * 2048 + qt * 128 + m_off + lr;
    const size_t mrow1 = mrow0 + 8;
#pragma unroll
    for (int nf = 0; nf < 16; nf++) {
#pragma unroll
        for (int jj = 0; jj < 2; jj++) {
            int dl = 2 * lc + jj;                         // 0..7 within 8-block
            size_t cslot = (size_t)(h * 16 + nf) * 8 + (dl & 3) * 2 + (dl >> 2);
            AP[mrow0 * 2048 + cslot] = to_tf32(o[nf][jj] * inv0);
            AP[mrow1 * 2048 + cslot] = to_tf32(o[nf][2 + jj] * inv1);
        }
    }
}

// ---------------------------------------------------------------------------

extern "C" void kernel_launch(void* const* d_in, const int* in_sizes, int n_in,
                              void* d_out, int out_size)
{
    const float* x  = (const float*)d_in[0];
    const float* Wq = (const float*)d_in[1];
    const float* bq = (const float*)d_in[2];
    const float* Wk = (const float*)d_in[3];
    const float* bk = (const float*)d_in[4];
    const float* Wv = (const float*)d_in[5];
    const float* bv = (const float*)d_in[6];
    const float* Wd = (const float*)d_in[7];
    const float* bd = (const float*)d_in[8];

    float* out = (float*)d_out;
    float* a_out = out;
    float* k_out = out + (size_t)Bb * Ss * Dd;
    float* v_out = k_out + (size_t)Bb * Ss * Dd;

    float *xp, *wpq, *wpk, *wpv, *wpd, *qp, *kp, *vp, *ap;
    cudaGetSymbolAddress((void**)&xp,  g_XP);
    cudaGetSymbolAddress((void**)&wpq, g_WPq);
    cudaGetSymbolAddress((void**)&wpk, g_WPk);
    cudaGetSymbolAddress((void**)&wpv, g_WPv);
    cudaGetSymbolAddress((void**)&wpd, g_WPd);
    cudaGetSymbolAddress((void**)&qp,  g_QP);
    cudaGetSymbolAddress((void**)&kp,  g_KP);
    cudaGetSymbolAddress((void**)&vp,  g_VP);
    cudaGetSymbolAddress((void**)&ap,  g_AP);

    xprep<<<Mtot, 256>>>(x, xp);
    wprep<<<dim3(8, 256), 256>>>(Wq, wpq);
    wprep<<<dim3(8, 256), 256>>>(Wk, wpk);
    wprep<<<dim3(8, 256), 256>>>(Wv, wpv);
    wprep<<<dim3(8, 256), 256>>>(Wd, wpd);

    dim3 gg(Dd / 128, Mtot / 128);
    size_t gsm = 2 * (size_t)GBUF2 * sizeof(float2);
    cudaFuncSetAttribute(gemm_tc, cudaFuncAttributeMaxDynamicSharedMemorySize, (int)gsm);

    gemm_tc<<<gg, 256, gsm>>>(xp, wpq, bq, nullptr, qp, 1);
    gemm_tc<<<gg, 256, gsm>>>(xp, wpk, bk, k_out, kp, 2);
    gemm_tc<<<gg, 256, gsm>>>(xp, wpv, bv, v_out, vp, 3);

    size_t asm_ = (size_t)(SQ2 + 2 * SK2 + 2 * SV2) * sizeof(float2);
    cudaFuncSetAttribute(attn_tc, cudaFuncAttributeMaxDynamicSharedMemorySize, (int)asm_);
    attn_tc<<<dim3(Ss / 128, Bb * Hh), 256, asm_>>>(qp, kp, vp, ap);

    gemm_tc<<<gg, 256, gsm>>>(ap, wpd, bd, a_out, nullptr, 0);
}

// round 8
// speedup vs baseline: 1.1400x; 1.0048x over previous
#include <cuda_runtime.h>
#include <cstdint>

#define Bb 2
#define Ss 2048
#define Dd 2048
#define Hh 16
#define HD 128
#define Mtot (Bb*Ss)

// Paired-tf32 global scratch (R3 layout).
// XP/AP: [Mtot][2048] floats:   addr = m*2048 + (k>>3)*8 + (k&3)*2 + ((k>>2)&1)
// WP:    [K/8][N][8 floats]:    addr = (k>>3)*16384 + n*8 + (k&3)*2 + ((k>>2)&1)
// QP/KP: per bh [Ss][128]:      addr = (bh*Ss+s)*128 + (d>>3)*8 + (d&3)*2 + ((d>>2)&1)
// VP:    per bh [128 d][2048]:  addr = (bh*128+d)*2048 + (s>>3)*8 + (s&3)*2 + ((s>>2)&1)
__device__ float g_XP[(size_t)Mtot * Dd];
__device__ float g_WPq[(size_t)Dd * Dd];
__device__ float g_WPk[(size_t)Dd * Dd];
__device__ float g_WPv[(size_t)Dd * Dd];
__device__ float g_WPd[(size_t)Dd * Dd];
__device__ float g_QP[(size_t)Mtot * Dd];
__device__ float g_KP[(size_t)Mtot * Dd];
__device__ float g_VP[(size_t)Mtot * Dd];
__device__ float g_AP[(size_t)Mtot * Dd];

__device__ __forceinline__ float to_tf32(float x) {
    float r;
    asm("cvt.rna.tf32.f32 %0, %1;" : "=f"(r) : "f"(x));
    return r;
}
__device__ __forceinline__ uint32_t u32(float x) { return __float_as_uint(x); }

__device__ __forceinline__ void mma8(float* c, const uint32_t* a, const uint32_t* b) {
    asm volatile(
        "mma.sync.aligned.m16n8k8.row.col.f32.tf32.tf32.f32 "
        "{%0,%1,%2,%3}, {%4,%5,%6,%7}, {%8,%9}, {%0,%1,%2,%3};"
        : "+f"(c[0]), "+f"(c[1]), "+f"(c[2]), "+f"(c[3])
        : "r"(a[0]), "r"(a[1]), "r"(a[2]), "r"(a[3]), "r"(b[0]), "r"(b[1]));
}
__device__ __forceinline__ void cpa16(void* dst, const void* src) {
    uint32_t d = (uint32_t)__cvta_generic_to_shared(dst);
    asm volatile("cp.async.cg.shared.global [%0], [%1], 16;" :: "r"(d), "l"(src));
}
#define CP_COMMIT asm volatile("cp.async.commit_group;")
#define CP_WAIT1  asm volatile("cp.async.wait_group 1;")
#define CP_WAIT0  asm volatile("cp.async.wait_group 0;")

// ---------------------------------------------------------------------------
// Fast prep kernels (R6, verified). wprep4 does all 4 weight matrices.
// ---------------------------------------------------------------------------
__global__ void xprep(const float* __restrict__ X, float* __restrict__ XP) {
    __shared__ float s[2048 + 256];            // addr(g) = g + (g>>3)
    const int m = blockIdx.x;
    const int tid = threadIdx.x;
    const float* src = X + (size_t)m * 2048;
#pragma unroll
    for (int i = 0; i < 2; i++) {
        int f = i * 256 + tid;
        float4 v = *(const float4*)(src + f * 4);
        float* d = s + f * 4 + (f >> 1);       // scalar STS (padded addr not 16B-aligned)
        d[0] = v.x; d[1] = v.y; d[2] = v.z; d[3] = v.w;
    }
    __syncthreads();
    const float* b = s + tid * 9;
    float4 o0 = make_float4(to_tf32(b[0]), to_tf32(b[4]), to_tf32(b[1]), to_tf32(b[5]));
    float4 o1 = make_float4(to_tf32(b[2]), to_tf32(b[6]), to_tf32(b[3]), to_tf32(b[7]));
    float* dst = XP + (size_t)m * 2048 + tid * 8;
    *(float4*)(dst) = o0;
    *(float4*)(dst + 4) = o1;
}

__global__ void wprep4(const float* __restrict__ W0, const float* __restrict__ W1,
                       const float* __restrict__ W2, const float* __restrict__ W3,
                       float* __restrict__ P0, float* __restrict__ P1,
                       float* __restrict__ P2, float* __restrict__ P3) {
    __shared__ float s[8 * 260];
    const int n0 = blockIdx.x * 256;
    const int kb = blockIdx.y;                 // 0..255
    const int z  = blockIdx.z;                 // which matrix
    const int tid = threadIdx.x;
    const float* W = (z == 0) ? W0 : (z == 1) ? W1 : (z == 2) ? W2 : W3;
    float* WP      = (z == 0) ? P0 : (z == 1) ? P1 : (z == 2) ? P2 : P3;
#pragma unroll
    for (int i = 0; i < 2; i++) {
        int f = i * 256 + tid;
        int r = f >> 6, c4 = (f & 63) * 4;
        float4 v = *(const float4*)(W + (size_t)(kb * 8 + r) * 2048 + n0 + c4);
        *(float4*)(s + r * 260 + c4) = v;
    }
    __syncthreads();
    const int n = tid;
    float4 o0 = make_float4(to_tf32(s[0 * 260 + n]), to_tf32(s[4 * 260 + n]),
                            to_tf32(s[1 * 260 + n]), to_tf32(s[5 * 260 + n]));
    float4 o1 = make_float4(to_tf32(s[2 * 260 + n]), to_tf32(s[6 * 260 + n]),
                            to_tf32(s[3 * 260 + n]), to_tf32(s[7 * 260 + n]));
    float* dst = WP + (size_t)kb * 16384 + (size_t)(n0 + n) * 8;
    *(float4*)(dst) = o0;
    *(float4*)(dst + 4) = o1;
}

// ---------------------------------------------------------------------------
// Pipelined tf32 GEMM on pre-paired operands (R3 schedule, unchanged).
// ---------------------------------------------------------------------------
#define ABUF2 (128*20)
#define BBUF2 (4*128*4)
#define GBUF2 (ABUF2 + BBUF2)

__global__ __launch_bounds__(256, 2)
void gemm_tc(const float* __restrict__ Ap, const float* __restrict__ WP,
             const float* __restrict__ bias, float* __restrict__ Craw,
             float* __restrict__ Cpair, int mode)
{
    extern __shared__ float2 sm2[];

    const int tid  = threadIdx.x;
    const int lane = tid & 31;
    const int wid  = tid >> 5;
    const int mb   = (wid >> 1) * 32;
    const int nb   = (wid & 1) * 64;
    const int lr   = lane >> 2;
    const int lc   = lane & 3;
    const int bx   = blockIdx.x;
    const int by   = blockIdx.y;

    float acc[2][8][4];
#pragma unroll
    for (int f = 0; f < 2; f++)
#pragma unroll
        for (int g = 0; g < 8; g++)
#pragma unroll
            for (int t = 0; t < 4; t++) acc[f][g][t] = 0.f;

    auto issue = [&](int kt, int buf) {
        float2* As = sm2 + buf * GBUF2;
        float2* Bs = As + ABUF2;
#pragma unroll
        for (int j = 0; j < 4; j++) {
            int idx = j * 256 + tid;
            int m   = idx >> 3;
            int ch  = idx & 7;
            cpa16(As + m * 20 + ch * 2,
                  Ap + (size_t)(by * 128 + m) * 2048 + kt * 32 + ch * 4);
        }
#pragma unroll
        for (int j = 0; j < 4; j++) {
            int idx = j * 256 + tid;
            int kb  = idx >> 8;
            int r   = idx & 255;
            int n   = r >> 1;
            int ch  = r & 1;
            cpa16(Bs + kb * 512 + n * 4 + ch * 2,
                  WP + (size_t)(kt * 4 + kb) * 16384 + (size_t)(bx * 128 + n) * 8 + ch * 4);
        }
    };

    issue(0, 0);
    CP_COMMIT;

    for (int kt = 0; kt < 64; kt++) {
        CP_WAIT0;
        __syncthreads();
        if (kt < 63) { issue(kt + 1, (kt + 1) & 1); CP_COMMIT; }

        const float2* As = sm2 + (kt & 1) * GBUF2;
        const float2* Bs = As + ABUF2;

#pragma unroll
        for (int ks = 0; ks < 4; ks++) {
            const float2* ap = As + (mb + lr) * 20 + ks * 4 + lc;
            float2 x00 = ap[0], x01 = ap[160], x10 = ap[320], x11 = ap[480];
            uint32_t a0[4] = {u32(x00.x), u32(x01.x), u32(x00.y), u32(x01.y)};
            uint32_t a1[4] = {u32(x10.x), u32(x11.x), u32(x10.y), u32(x11.y)};
            const float2* bp = Bs + ks * 512 + (nb + lr) * 4 + lc;
#pragma unroll
            for (int g = 0; g < 8; g++) {
                float2 bv = bp[g * 32];
                uint32_t b[2] = {u32(bv.x), u32(bv.y)};
                mma8(acc[0][g], a0, b);
                mma8(acc[1][g], a1, b);
            }
        }
        __syncthreads();
    }

    const float qscale = 0.08838834764831845f;   // folded into Q when mode==1
#pragma unroll
    for (int f = 0; f < 2; f++) {
#pragma unroll
        for (int g = 0; g < 8; g++) {
#pragma unroll
            for (int ii = 0; ii < 2; ii++) {
                int row = by * 128 + mb + f * 16 + lr + 8 * ii;
#pragma unroll
                for (int jj = 0; jj < 2; jj++) {
                    int col = bx * 128 + nb + g * 8 + lc * 2 + jj;
                    float v = acc[f][g][ii * 2 + jj] + bias[col];
                    if (mode == 0) {
                        Craw[(size_t)row * Dd + col] = v;
                    } else {
                        int b_ = row >> 11, s_ = row & 2047;
                        int h_ = col >> 7,  d_ = col & 127;
                        size_t bh = (size_t)(b_ * Hh + h_);
                        if (mode >= 2) Craw[(bh * Ss + s_) * HD + d_] = v;
                        if (mode == 3) {
                            Cpair[(bh * 128 + d_) * 2048 +
                                  (s_ >> 3) * 8 + (s_ & 3) * 2 + ((s_ >> 2) & 1)] = to_tf32(v);
                        } else {
                            float tv = (mode == 1) ? to_tf32(v * qscale) : to_tf32(v);
                            Cpair[(bh * Ss + s_) * 128 +
                                  (d_ >> 3) * 8 + (d_ & 3) * 2 + ((d_ >> 2) & 1)] = tv;
                        }
                    }
                }
            }
        }
    }
}

// ---------------------------------------------------------------------------
// Single-pass tf32 flash attention. Q fragments hoisted to registers (loaded
// once per block); corr==1 rescale skip. Otherwise R6 schedule.
// ---------------------------------------------------------------------------
#define QS2 68
#define KS2 68
#define VS2 36
#define SQ2 (128*QS2)
#define SK2 (64*KS2)
#define SV2 (128*VS2)

__global__ __launch_bounds__(256)
void attn_tc(const float* __restrict__ QP, const float* __restrict__ KP,
             const float* __restrict__ VP, float* __restrict__ AP)
{
    extern __shared__ float2 sm2[];
    float2* sQ = sm2;                  // SQ2
    float2* sK = sQ + SQ2;             // 2*SK2
    float2* sV = sK + 2 * SK2;         // 2*SV2

    const int qt  = (gridDim.x - 1) - blockIdx.x;
    const int bh  = blockIdx.y;
    const int tid = threadIdx.x;
    const int lane = tid & 31;
    const int wid  = tid >> 5;
    const int lr   = lane >> 2;
    const int lc   = lane & 3;
    const int m_off = wid * 16;

    const float* Qg = QP + ((size_t)bh * Ss + (size_t)qt * 128) * 128;
    const float* Kg = KP + (size_t)bh * Ss * 128;
    const float* Vg = VP + (size_t)bh * 128 * 2048;

    // Group 0: Q tile
#pragma unroll
    for (int i = 0; i < 16; i++) {
        int idx = i * 256 + tid;
        int row = idx >> 5;
        int ch  = idx & 31;
        cpa16(sQ + row * QS2 + ch * 2, Qg + (size_t)row * 128 + ch * 4);
    }
    CP_COMMIT;
    // Group 1: KV tile 0
#pragma unroll
    for (int i = 0; i < 8; i++) {
        int idx = i * 256 + tid;
        int row = idx >> 5;
        int ch  = idx & 31;
        cpa16(sK + row * KS2 + ch * 2, Kg + (size_t)row * 128 + ch * 4);
    }
#pragma unroll
    for (int i = 0; i < 8; i++) {
        int idx = i * 256 + tid;
        int d   = idx >> 4;
        int ch  = idx & 15;
        cpa16(sV + d * VS2 + ch * 2, Vg + (size_t)d * 2048 + ch * 4);
    }
    CP_COMMIT;

    // Wait for Q (group 0), then hoist Q fragments into registers.
    CP_WAIT1;
    __syncthreads();
    uint32_t qf[16][4];
#pragma unroll
    for (int ks = 0; ks < 16; ks++) {
        const float2* qp = sQ + (m_off + lr) * QS2 + ks * 4 + lc;
        float2 q0 = qp[0], q1 = qp[8 * QS2];
        qf[ks][0] = u32(q0.x); qf[ks][1] = u32(q1.x);
        qf[ks][2] = u32(q0.y); qf[ks][3] = u32(q1.y);
    }

    float o[16][4];
#pragma unroll
    for (int n = 0; n < 16; n++)
#pragma unroll
        for (int j = 0; j < 4; j++) o[n][j] = 0.f;
    float m0 = -1e30f, m1 = -1e30f, l0 = 0.f, l1 = 0.f;

    const int tmax = 2 * qt + 1;
    const int warp_max_row = qt * 128 + m_off + 15;

    for (int t = 0; t <= tmax; t++) {
        const int buf = t & 1;
        if (t < tmax) {
            const int nb2 = (t + 1) & 1;
            float2* dK = sK + nb2 * SK2;
            float2* dV = sV + nb2 * SV2;
            const float* gK = Kg + (size_t)(t + 1) * 64 * 128;
            const float* gV = Vg + (size_t)(t + 1) * 64;
#pragma unroll
            for (int i = 0; i < 8; i++) {
                int idx = i * 256 + tid;
                int row = idx >> 5;
                int ch  = idx & 31;
                cpa16(dK + row * KS2 + ch * 2, gK + (size_t)row * 128 + ch * 4);
            }
#pragma unroll
            for (int i = 0; i < 8; i++) {
                int idx = i * 256 + tid;
                int d   = idx >> 4;
                int ch  = idx & 15;
                cpa16(dV + d * VS2 + ch * 2, gV + (size_t)d * 2048 + ch * 4);
            }
            CP_COMMIT;
            CP_WAIT1;
        } else {
            CP_WAIT0;
        }
        __syncthreads();

        if (t * 64 <= warp_max_row) {    // skip fully-masked warp tiles
            const float2* sKb = sK + buf * SK2;
            const float2* sVb = sV + buf * SV2;

            // ---- S = Q @ K^T (Q pre-scaled, frags in regs), warp tile 16x64 ----
            float c[8][4];
#pragma unroll
            for (int n = 0; n < 8; n++)
#pragma unroll
                for (int j = 0; j < 4; j++) c[n][j] = 0.f;

#pragma unroll
            for (int ks = 0; ks < 16; ks++) {
                const float2* kp = sKb + lr * KS2 + ks * 4 + lc;
#pragma unroll
                for (int nf = 0; nf < 8; nf++) {
                    float2 bv = kp[nf * 8 * KS2];
                    uint32_t b[2] = {u32(bv.x), u32(bv.y)};
                    mma8(c[nf], qf[ks], b);
                }
            }

            // ---- causal mask ----
            if (t * 64 + 63 > qt * 128 + m_off) {
#pragma unroll
                for (int nf = 0; nf < 8; nf++) {
#pragma unroll
                    for (int j = 0; j < 4; j++) {
                        int col = t * 64 + nf * 8 + 2 * lc + (j & 1);
                        int row = qt * 128 + m_off + lr + 8 * (j >> 1);
                        if (col > row) c[nf][j] = -1e30f;
                    }
                }
            }

            // ---- online softmax (rows lr, lr+8) ----
            float mt0 = -1e30f, mt1 = -1e30f;
#pragma unroll
            for (int nf = 0; nf < 8; nf++) {
                mt0 = fmaxf(mt0, fmaxf(c[nf][0], c[nf][1]));
                mt1 = fmaxf(mt1, fmaxf(c[nf][2], c[nf][3]));
            }
#pragma unroll
            for (int d = 1; d <= 2; d <<= 1) {
                mt0 = fmaxf(mt0, __shfl_xor_sync(0xffffffffu, mt0, d));
                mt1 = fmaxf(mt1, __shfl_xor_sync(0xffffffffu, mt1, d));
            }
            float nm0 = fmaxf(m0, mt0), nm1 = fmaxf(m1, mt1);
            float corr0 = __expf(m0 - nm0), corr1 = __expf(m1 - nm1);
            m0 = nm0; m1 = nm1;

            float s0 = 0.f, s1 = 0.f;
#pragma unroll
            for (int nf = 0; nf < 8; nf++) {
                c[nf][0] = __expf(c[nf][0] - nm0); s0 += c[nf][0];
                c[nf][1] = __expf(c[nf][1] - nm0); s0 += c[nf][1];
                c[nf][2] = __expf(c[nf][2] - nm1); s1 += c[nf][2];
                c[nf][3] = __expf(c[nf][3] - nm1); s1 += c[nf][3];
            }
#pragma unroll
            for (int d = 1; d <= 2; d <<= 1) {
                s0 += __shfl_xor_sync(0xffffffffu, s0, d);
                s1 += __shfl_xor_sync(0xffffffffu, s1, d);
            }
            l0 = l0 * corr0 + s0;
            l1 = l1 * corr1 + s1;

            if (__any_sync(0xffffffffu, (corr0 != 1.f) || (corr1 != 1.f))) {
#pragma unroll
                for (int n = 0; n < 16; n++) {
                    o[n][0] *= corr0; o[n][1] *= corr0;
                    o[n][2] *= corr1; o[n][3] *= corr1;
                }
            }

            // ---- O += P @ V, warp tile 16x128 ----
#pragma unroll
            for (int ks = 0; ks < 8; ks++) {
                const int src0 = 4 * lr + (lc >> 1);
                const int src1 = src0 + 2;
                float v00 = __shfl_sync(0xffffffffu, c[ks][0], src0);
                float v01 = __shfl_sync(0xffffffffu, c[ks][1], src0);
                float v20 = __shfl_sync(0xffffffffu, c[ks][2], src0);
                float v21 = __shfl_sync(0xffffffffu, c[ks][3], src0);
                float w00 = __shfl_sync(0xffffffffu, c[ks][0], src1);
                float w01 = __shfl_sync(0xffffffffu, c[ks][1], src1);
                float w20 = __shfl_sync(0xffffffffu, c[ks][2], src1);
                float w21 = __shfl_sync(0xffffffffu, c[ks][3], src1);
                float a0f = (lc & 1) ? v01 : v00;
                float a1f = (lc & 1) ? v21 : v20;
                float a2f = (lc & 1) ? w01 : w00;
                float a3f = (lc & 1) ? w21 : w20;
                uint32_t a[4] = {u32(to_tf32(a0f)), u32(to_tf32(a1f)),
                                 u32(to_tf32(a2f)), u32(to_tf32(a3f))};
                const float2* vp = sVb + lr * VS2 + ks * 4 + lc;
#pragma unroll
                for (int nf = 0; nf < 16; nf++) {
                    float2 bv = vp[nf * 8 * VS2];
                    uint32_t b[2] = {u32(bv.x), u32(bv.y)};
                    mma8(o[nf], a, b);
                }
            }
        }
        __syncthreads();
    }

    // ---- epilogue: normalize, convert, write pre-paired AP ----
    const float inv0 = 1.0f / l0;
    const float inv1 = 1.0f / l1;
    const int b = bh / Hh;
    const int h = bh % Hh;
    const size_t mrow0 = (size_t)b * 2048 + qt * 128 + m_off + lr;
    const size_t mrow1 = mrow0 + 8;
#pragma unroll
    for (int nf = 0; nf < 16; nf++) {
#pragma unroll
        for (int jj = 0; jj < 2; jj++) {
            int dl = 2 * lc + jj;
            size_t cslot = (size_t)(h * 16 + nf) * 8 + (dl & 3) * 2 + (dl >> 2);
            AP[mrow0 * 2048 + cslot] = to_tf32(o[nf][jj] * inv0);
            AP[mrow1 * 2048 + cslot] = to_tf32(o[nf][2 + jj] * inv1);
        }
    }
}

// ---------------------------------------------------------------------------

extern "C" void kernel_launch(void* const* d_in, const int* in_sizes, int n_in,
                              void* d_out, int out_size)
{
    const float* x  = (const float*)d_in[0];
    const float* Wq = (const float*)d_in[1];
    const float* bq = (const float*)d_in[2];
    const float* Wk = (const float*)d_in[3];
    const float* bk = (const float*)d_in[4];
    const float* Wv = (const float*)d_in[5];
    const float* bv = (const float*)d_in[6];
    const float* Wd = (const float*)d_in[7];
    const float* bd = (const float*)d_in[8];

    float* out = (float*)d_out;
    float* a_out = out;
    float* k_out = out + (size_t)Bb * Ss * Dd;
    float* v_out = k_out + (size_t)Bb * Ss * Dd;

    float *xp, *wpq, *wpk, *wpv, *wpd, *qp, *kp, *vp, *ap;
    cudaGetSymbolAddress((void**)&xp,  g_XP);
    cudaGetSymbolAddress((void**)&wpq, g_WPq);
    cudaGetSymbolAddress((void**)&wpk, g_WPk);
    cudaGetSymbolAddress((void**)&wpv, g_WPv);
    cudaGetSymbolAddress((void**)&wpd, g_WPd);
    cudaGetSymbolAddress((void**)&qp,  g_QP);
    cudaGetSymbolAddress((void**)&kp,  g_KP);
    cudaGetSymbolAddress((void**)&vp,  g_VP);
    cudaGetSymbolAddress((void**)&ap,  g_AP);

    xprep<<<Mtot, 256>>>(x, xp);
    wprep4<<<dim3(8, 256, 4), 256>>>(Wq, Wk, Wv, Wd, wpq, wpk, wpv, wpd);

    dim3 gg(Dd / 128, Mtot / 128);
    size_t gsm = 2 * (size_t)GBUF2 * sizeof(float2);
    cudaFuncSetAttribute(gemm_tc, cudaFuncAttributeMaxDynamicSharedMemorySize, (int)gsm);

    gemm_tc<<<gg, 256, gsm>>>(xp, wpq, bq, nullptr, qp, 1);
    gemm_tc<<<gg, 256, gsm>>>(xp, wpk, bk, k_out, kp, 2);
    gemm_tc<<<gg, 256, gsm>>>(xp, wpv, bv, v_out, vp, 3);

    size_t asm_ = (size_t)(SQ2 + 2 * SK2 + 2 * SV2) * sizeof(float2);
    cudaFuncSetAttribute(attn_tc, cudaFuncAttributeMaxDynamicSharedMemorySize, (int)asm_);
    attn_tc<<<dim3(Ss / 128, Bb * Hh), 256, asm_>>>(qp, kp, vp, ap);

    gemm_tc<<<gg, 256, gsm>>>(ap, wpd, bd, a_out, nullptr, 0);
}